// round 15
// baseline (speedup 1.0000x reference)
#include <cuda_runtime.h>
#include <cuda_bf16.h>
#include <math.h>
#include <stdint.h>

#define D     128
#define NLIT  8000
#define NLITP 8064          // padded to 63*128
#define NCLS  16000         // = 125*128
#define GD    512
#define NNZ_MAX 480000

#define LDT 40              // smem tile row stride in bf16 (32 + 8 pad)
typedef __nv_bfloat16 bf16;

// ---------------- persistent scratch (device globals) -----------------------
__device__ bf16 g_Lh[NLITP*D],     g_Lm[NLITP*D],     g_Ll[NLITP*D];
__device__ bf16 g_hLh[NLITP*D],    g_hLm[NLITP*D],    g_hLl[NLITP*D];
__device__ bf16 g_msgsLh[NLITP*D], g_msgsLm[NLITP*D], g_msgsLl[NLITP*D];
__device__ bf16 g_hCh[NCLS*D],     g_hCm[NCLS*D],     g_hCl[NCLS*D];
__device__ bf16 g_Csh[NCLS*D],     g_Csm[NCLS*D],     g_Csl[NCLS*D];
__device__ bf16 g_msgsCh[NCLS*D],  g_msgsCm[NCLS*D],  g_msgsCl[NCLS*D];
__device__ bf16 g_WCh[GD*2*D],     g_WCm[GD*2*D],     g_WCl[GD*2*D];
__device__ bf16 g_WLh[GD*3*D],     g_WLm[GD*3*D],     g_WLl[GD*3*D];
__device__ bf16 g_Wlch[D*D],       g_Wlcm[D*D],       g_Wlcl[D*D];
__device__ bf16 g_Wclh[D*D],       g_Wclm[D*D],       g_Wcll[D*D];
__device__ float g_pre[NCLS * D];
__device__ float g_gates[NCLS * GD];
__device__ float g_cC[NCLS * D];
__device__ float g_cL[NLIT * D];
__device__ float g_L32[NLIT * D];
__device__ float g_bC[GD];
__device__ float g_bL[GD];
__device__ int g_lit_ptr[NLIT + 1];
__device__ int g_cls_ptr[NCLS + 1];
__device__ int g_lit_idx[NNZ_MAX];
__device__ int g_cls_idx[NNZ_MAX];
__device__ int g_lit_cnt[NLIT];
__device__ int g_cls_cnt[NCLS];
__device__ int g_pair_l[NNZ_MAX];
__device__ int g_pair_c[NNZ_MAX];
__device__ int g_nnz[1];

// ---------------- helpers ----------------------------------------------------
__device__ __forceinline__ uint32_t s2u(const void* p) {
    uint32_t a;
    asm("{ .reg .u64 t; cvta.to.shared.u64 t, %1; cvt.u32.u64 %0, t; }" : "=r"(a) : "l"(p));
    return a;
}

#define LDSM_X4(r0, r1, r2, r3, addr) \
    asm volatile("ldmatrix.sync.aligned.m8n8.x4.shared.b16 {%0,%1,%2,%3}, [%4];" \
                 : "=r"(r0), "=r"(r1), "=r"(r2), "=r"(r3) : "r"(addr))

#define MMAB(c, a, b0v, b1v) \
    asm volatile("mma.sync.aligned.m16n8k16.row.col.f32.bf16.bf16.f32 " \
                 "{%0,%1,%2,%3}, {%4,%5,%6,%7}, {%8,%9}, {%0,%1,%2,%3};" \
                 : "+f"((c)[0]), "+f"((c)[1]), "+f"((c)[2]), "+f"((c)[3]) \
                 : "r"((a)[0]), "r"((a)[1]), "r"((a)[2]), "r"((a)[3]), \
                   "r"(b0v), "r"(b1v))

__device__ __forceinline__ void split3(float x, bf16& h, bf16& m, bf16& l) {
    h = __float2bfloat16_rn(x);
    float r1 = x - __bfloat162float(h);
    m = __float2bfloat16_rn(r1);
    float r2 = r1 - __bfloat162float(m);
    l = __float2bfloat16_rn(r2);
}

// -------- triple-split bf16 GEMM, unchained-main accumulation ---------------
// C[M x N] = catA[M x K] * B[N x K]^T + bias, fp32 out.
// hi*hi products issued on a zeroed accumulator each k-step and summed with
// RN FADDs (kills RZ chaining bias); 5 small correction products chain in a
// separate accumulator (bias scaled by 2^-8 => negligible).
// CTA tile 128x64; 8 warps; warp tile 32x32.
__global__ void __launch_bounds__(256) gemm_t3(
    const bf16* __restrict__ A0h, const bf16* __restrict__ A0m, const bf16* __restrict__ A0l,
    const bf16* __restrict__ A1h, const bf16* __restrict__ A1m, const bf16* __restrict__ A1l,
    const bf16* __restrict__ A2h, const bf16* __restrict__ A2m, const bf16* __restrict__ A2l,
    int nseg,
    const bf16* __restrict__ Bh, const bf16* __restrict__ Bm, const bf16* __restrict__ Bl,
    const float* __restrict__ bias, float* __restrict__ Cout, int N)
{
    __shared__ __align__(16) bf16 As[3][128 * LDT];
    __shared__ __align__(16) bf16 Bs[3][64 * LDT];
    const int tid = threadIdx.x;
    const int wid = tid >> 5, lid = tid & 31;
    const int warp_m = wid & 3, warp_n = wid >> 2;   // 4 x 2
    const int g  = lid >> 2, tg = lid & 3;
    const int quad = lid >> 3, lr = lid & 7;
    const int K = nseg * 128;
    const int m0 = blockIdx.y * 128, n0 = blockIdx.x * 64;
    const bf16* segA[3][3] = {{A0h, A1h, A2h}, {A0m, A1m, A2m}, {A0l, A1l, A2l}};
    const bf16* segB[3] = {Bh, Bm, Bl};
    uint32_t As_s[3], Bs_s[3];
#pragma unroll
    for (int v = 0; v < 3; v++) { As_s[v] = s2u(As[v]); Bs_s[v] = s2u(Bs[v]); }

    float tot[2][4][4], corr[2][4][4];
#pragma unroll
    for (int i = 0; i < 2; i++)
#pragma unroll
        for (int j = 0; j < 4; j++)
#pragma unroll
            for (int q = 0; q < 4; q++) { tot[i][j][q] = 0.f; corr[i][j][q] = 0.f; }

    for (int k0 = 0; k0 < K; k0 += 32) {
        const int seg = k0 >> 7;
        const int ko = k0 & 127;
        // load 3 levels of A (128x32) and B (64x32)
        for (int v = tid; v < 3 * 768; v += 256) {
            int lvl = v / 768;
            int rr = v % 768;
            int r = rr >> 2, c4 = rr & 3;
            if (r < 128) {
                *(float4*)(As[lvl] + r * LDT + c4 * 8) =
                    *(const float4*)(segA[lvl][seg] + (size_t)(m0 + r) * 128 + ko + c4 * 8);
            } else {
                int rb = r - 128;
                *(float4*)(Bs[lvl] + rb * LDT + c4 * 8) =
                    *(const float4*)(segB[lvl] + (size_t)(n0 + rb) * K + k0 + c4 * 8);
            }
        }
        __syncthreads();

#pragma unroll
        for (int kk = 0; kk < 32; kk += 16) {
            uint32_t a[3][2][4], b[3][2][4];
#pragma unroll
            for (int mt = 0; mt < 2; mt++) {
                uint32_t off = (uint32_t)((warp_m * 32 + mt * 16 + (quad & 1) * 8 + lr) * LDT
                                          + kk + (quad >> 1) * 8) * 2;
#pragma unroll
                for (int lvl = 0; lvl < 3; lvl++)
                    LDSM_X4(a[lvl][mt][0], a[lvl][mt][1], a[lvl][mt][2], a[lvl][mt][3],
                            As_s[lvl] + off);
            }
#pragma unroll
            for (int p = 0; p < 2; p++) {
                uint32_t off = (uint32_t)((warp_n * 32 + p * 16 + (quad >> 1) * 8 + lr) * LDT
                                          + kk + (quad & 1) * 8) * 2;
#pragma unroll
                for (int lvl = 0; lvl < 3; lvl++)
                    LDSM_X4(b[lvl][p][0], b[lvl][p][1], b[lvl][p][2], b[lvl][p][3],
                            Bs_s[lvl] + off);
            }
#pragma unroll
            for (int mt = 0; mt < 2; mt++)
#pragma unroll
                for (int p = 0; p < 2; p++) {
                    // corrections: (ia,ib) with 1 <= ia+ib <= 2, chained in corr
#pragma unroll
                    for (int ia = 0; ia < 3; ia++)
#pragma unroll
                        for (int ib = 0; ib < 3; ib++) {
                            int s = ia + ib;
                            if (s < 1 || s > 2) continue;
                            MMAB(corr[mt][2*p],   a[ia][mt], b[ib][p][0], b[ib][p][1]);
                            MMAB(corr[mt][2*p+1], a[ia][mt], b[ib][p][2], b[ib][p][3]);
                        }
                    // hi*hi: zeroed accumulator, RN FADD into tot
                    float dd[4];
                    dd[0] = dd[1] = dd[2] = dd[3] = 0.f;
                    MMAB(dd, a[0][mt], b[0][p][0], b[0][p][1]);
#pragma unroll
                    for (int q = 0; q < 4; q++) tot[mt][2*p][q] += dd[q];
                    dd[0] = dd[1] = dd[2] = dd[3] = 0.f;
                    MMAB(dd, a[0][mt], b[0][p][2], b[0][p][3]);
#pragma unroll
                    for (int q = 0; q < 4; q++) tot[mt][2*p+1][q] += dd[q];
                }
        }
        __syncthreads();
    }

    // epilogue: out = tot + corr + bias (fp32)
#pragma unroll
    for (int mt = 0; mt < 2; mt++) {
        int row = m0 + warp_m * 32 + mt * 16 + g;
#pragma unroll
        for (int nt = 0; nt < 4; nt++) {
            int col = n0 + warp_n * 32 + nt * 8 + 2 * tg;
            float bx = bias[col], by = bias[col + 1];
            *(float2*)(Cout + (size_t)row * N + col) =
                make_float2(tot[mt][nt][0] + corr[mt][nt][0] + bx,
                            tot[mt][nt][1] + corr[mt][nt][1] + by);
            *(float2*)(Cout + (size_t)(row + 8) * N + col) =
                make_float2(tot[mt][nt][2] + corr[mt][nt][2] + bx,
                            tot[mt][nt][3] + corr[mt][nt][3] + by);
        }
    }
}

// ---------------- SpMM (gather, fp32 accum, triple-split output) ------------
__global__ void spmm_s3(const int* __restrict__ ptr, const int* __restrict__ idx,
                        const float* __restrict__ src,
                        bf16* __restrict__ dh, bf16* __restrict__ dm,
                        bf16* __restrict__ dl) {
    int row = blockIdx.x;
    int d = threadIdx.x;  // 128
    int s = ptr[row], e = ptr[row + 1];
    float acc = 0.f;
    for (int j = s; j < e; j++) acc += __ldg(&src[(size_t)idx[j] * D + d]);
    bf16 h, m, l;
    split3(acc, h, m, l);
    size_t o = (size_t)row * D + d;
    dh[o] = h; dm[o] = m; dl[o] = l;
}

// ---------------- LSTM pointwise (fp32 math, triple-split outputs) ----------
__device__ __forceinline__ float sigm(float x) { return 1.f / (1.f + expf(-x)); }

__global__ void lstm_s3(const float* __restrict__ gates, float* __restrict__ c,
                        bf16* __restrict__ hh, bf16* __restrict__ hm, bf16* __restrict__ hl,
                        bf16* __restrict__ ch, bf16* __restrict__ cm, bf16* __restrict__ cl,
                        float* __restrict__ h32, int rows) {
    int n = rows * D;
    int stride = gridDim.x * blockDim.x;
    for (int i = blockIdx.x * blockDim.x + threadIdx.x; i < n; i += stride) {
        int row = i >> 7, d = i & 127;
        const float* gr = gates + (size_t)row * GD;
        float ig = gr[d], fg = gr[D + d], gg = gr[2 * D + d], og = gr[3 * D + d];
        float cn = sigm(fg) * c[i] + sigm(ig) * tanhf(gg);
        c[i] = cn;
        bf16 xh, xm, xl;
        split3(cn, xh, xm, xl);
        ch[i] = xh; cm[i] = xm; cl[i] = xl;
        float hn = sigm(og) * tanhf(cn);
        split3(hn, xh, xm, xl);
        hh[i] = xh; hm[i] = xm; hl[i] = xl;
        if (h32) h32[i] = hn;
    }
}

// ---------------- init / weight prep ----------------------------------------
__global__ void init_s3(const float* __restrict__ L, const float* __restrict__ hL,
                        const float* __restrict__ hC) {
    int stride = gridDim.x * blockDim.x;
    for (int i = blockIdx.x * blockDim.x + threadIdx.x; i < NCLS * D; i += stride) {
        bf16 xh, xm, xl;
        if (i < NLITP * D) {
            int r = i >> 7;
            float lv = (r < NLIT) ? L[i] : 0.f;
            float hv = (r < NLIT) ? hL[i] : 0.f;
            split3(lv, xh, xm, xl); g_Lh[i] = xh;  g_Lm[i] = xm;  g_Ll[i] = xl;
            split3(hv, xh, xm, xl); g_hLh[i] = xh; g_hLm[i] = xm; g_hLl[i] = xl;
            bf16 z = __float2bfloat16_rn(0.f);
            g_msgsLh[i] = z; g_msgsLm[i] = z; g_msgsLl[i] = z;
            if (r < NLIT) g_cL[i] = hv;
        }
        float cv = hC[i];
        split3(cv, xh, xm, xl);
        g_hCh[i] = xh; g_hCm[i] = xm; g_hCl[i] = xl;
        g_cC[i] = cv;
    }
}

__global__ void prep_w_s3(const float* __restrict__ Wlc, const float* __restrict__ Wcl,
                          const float* __restrict__ WihC, const float* __restrict__ WhhC,
                          const float* __restrict__ bihC, const float* __restrict__ bhhC,
                          const float* __restrict__ WihL, const float* __restrict__ WhhL,
                          const float* __restrict__ bihL, const float* __restrict__ bhhL) {
    int stride = gridDim.x * blockDim.x;
    int tid0 = blockIdx.x * blockDim.x + threadIdx.x;
    bf16 xh, xm, xl;
    for (int t = tid0; t < GD * 2 * D; t += stride) {
        int j = t / (2 * D), k = t % (2 * D);
        float v = (k < D) ? WihC[j * D + k] : WhhC[j * D + (k - D)];
        split3(v, xh, xm, xl); g_WCh[t] = xh; g_WCm[t] = xm; g_WCl[t] = xl;
    }
    for (int t = tid0; t < GD * 3 * D; t += stride) {
        int j = t / (3 * D), k = t % (3 * D);
        float v = (k < 2 * D) ? WihL[j * 2 * D + k] : WhhL[j * D + (k - 2 * D)];
        split3(v, xh, xm, xl); g_WLh[t] = xh; g_WLm[t] = xm; g_WLl[t] = xl;
    }
    for (int t = tid0; t < D * D; t += stride) {
        split3(Wlc[t], xh, xm, xl); g_Wlch[t] = xh; g_Wlcm[t] = xm; g_Wlcl[t] = xl;
        split3(Wcl[t], xh, xm, xl); g_Wclh[t] = xh; g_Wclm[t] = xm; g_Wcll[t] = xl;
    }
    for (int t = tid0; t < GD; t += stride) {
        g_bC[t] = bihC[t] + bhhC[t];
        g_bL[t] = bihL[t] + bhhL[t];
    }
}

// ---------------- misc utility ----------------------------------------------
__global__ void copy_f(float* __restrict__ dst, const float* __restrict__ src, int n) {
    int stride = gridDim.x * blockDim.x;
    for (int i = blockIdx.x * blockDim.x + threadIdx.x; i < n; i += stride)
        dst[i] = src[i];
}
__global__ void zero_i(int* __restrict__ p, int n) {
    int stride = gridDim.x * blockDim.x;
    for (int i = blockIdx.x * blockDim.x + threadIdx.x; i < n; i += stride)
        p[i] = 0;
}

// ---------------- CSR build (validated in R1) -------------------------------
__global__ void build_pairs(const float* __restrict__ M) {
    int l = blockIdx.y;
    const float4* row = (const float4*)(M + (size_t)l * NCLS);
    const int total4 = NCLS / 4;
    int lane = threadIdx.x & 31;
    int stride = gridDim.x * blockDim.x;
    int row_count = 0;
    for (int i = blockIdx.x * blockDim.x + threadIdx.x;; i += stride) {
        bool inb = i < total4;
        if (__ballot_sync(0xffffffffu, inb) == 0) break;
        float4 v = inb ? row[i] : make_float4(0.f, 0.f, 0.f, 0.f);
        float vv[4] = {v.x, v.y, v.z, v.w};
#pragma unroll
        for (int j = 0; j < 4; j++) {
            bool pred = vv[j] > 0.5f;
            unsigned act = __ballot_sync(0xffffffffu, pred);
            int tot = __popc(act);
            if (pred) {
                int rank = __popc(act & ((1u << lane) - 1u));
                int leader = __ffs(act) - 1;
                int base = 0;
                if (lane == leader) base = atomicAdd(&g_nnz[0], tot);
                base = __shfl_sync(act, base, leader);
                int p = base + rank;
                int c = i * 4 + j;
                if (p < NNZ_MAX) { g_pair_l[p] = l; g_pair_c[p] = c; }
                atomicAdd(&g_cls_cnt[c], 1);
            }
            row_count += tot;
        }
    }
    if (lane == 0 && row_count) atomicAdd(&g_lit_cnt[l], row_count);
}

__global__ void scan_excl(const int* __restrict__ cnt, int* __restrict__ ptr, int n) {
    const int T = 1024;
    __shared__ int part[T];
    int t = threadIdx.x;
    int chunk = (n + T - 1) / T;
    int s0 = t * chunk;
    int s1 = min(n, s0 + chunk);
    int s = 0;
    for (int i = s0; i < s1; i++) s += cnt[i];
    part[t] = s;
    __syncthreads();
    if (t == 0) {
        int run = 0;
        for (int i = 0; i < T; i++) { int v = part[i]; part[i] = run; run += v; }
        ptr[n] = run;
    }
    __syncthreads();
    int run = part[t];
    for (int i = s0; i < s1; i++) { ptr[i] = run; run += cnt[i]; }
}

__global__ void fill_csr() {
    int nnz = g_nnz[0];
    if (nnz > NNZ_MAX) nnz = NNZ_MAX;
    int stride = gridDim.x * blockDim.x;
    for (int i = blockIdx.x * blockDim.x + threadIdx.x; i < nnz; i += stride) {
        int l = g_pair_l[i], c = g_pair_c[i];
        int p = g_lit_ptr[l] + atomicAdd(&g_lit_cnt[l], 1);
        g_lit_idx[p] = c;
        int q = g_cls_ptr[c] + atomicAdd(&g_cls_cnt[c], 1);
        g_cls_idx[q] = l;
    }
}

// ---------------- driver ----------------------------------------------------
extern "C" void kernel_launch(void* const* d_in, const int* in_sizes, int n_in,
                              void* d_out, int out_size) {
    const float* L_state  = (const float*)d_in[0];
    const float* hidden_L = (const float*)d_in[2];
    const float* hidden_C = (const float*)d_in[3];
    const float* Mmat     = (const float*)d_in[4];
    const float* W_lc = (const float*)d_in[6];
    const float* b_lc = (const float*)d_in[7];
    const float* W_cl = (const float*)d_in[8];
    const float* b_cl = (const float*)d_in[9];
    const float* WihC = (const float*)d_in[10];
    const float* WhhC = (const float*)d_in[11];
    const float* bihC = (const float*)d_in[12];
    const float* bhhC = (const float*)d_in[13];
    const float* WihL = (const float*)d_in[14];
    const float* WhhL = (const float*)d_in[15];
    const float* bihL = (const float*)d_in[16];
    const float* bhhL = (const float*)d_in[17];
    float* out = (float*)d_out;

    bf16 *pLh,*pLm,*pLl,*phLh,*phLm,*phLl,*pMLh,*pMLm,*pMLl;
    bf16 *phCh,*phCm,*phCl,*pCsh,*pCsm,*pCsl,*pMCh,*pMCm,*pMCl;
    bf16 *pWCh,*pWCm,*pWCl,*pWLh,*pWLm,*pWLl,*pWlch,*pWlcm,*pWlcl,*pWclh,*pWclm,*pWcll;
    float *pPre,*pGates,*pcC,*pcL,*pL32,*pbC,*pbL;
    int *pLitPtr,*pClsPtr,*pLitIdx,*pClsIdx,*pLitCnt,*pClsCnt,*pNnz;
    cudaGetSymbolAddress((void**)&pLh, g_Lh);   cudaGetSymbolAddress((void**)&pLm, g_Lm);   cudaGetSymbolAddress((void**)&pLl, g_Ll);
    cudaGetSymbolAddress((void**)&phLh, g_hLh); cudaGetSymbolAddress((void**)&phLm, g_hLm); cudaGetSymbolAddress((void**)&phLl, g_hLl);
    cudaGetSymbolAddress((void**)&pMLh, g_msgsLh); cudaGetSymbolAddress((void**)&pMLm, g_msgsLm); cudaGetSymbolAddress((void**)&pMLl, g_msgsLl);
    cudaGetSymbolAddress((void**)&phCh, g_hCh); cudaGetSymbolAddress((void**)&phCm, g_hCm); cudaGetSymbolAddress((void**)&phCl, g_hCl);
    cudaGetSymbolAddress((void**)&pCsh, g_Csh); cudaGetSymbolAddress((void**)&pCsm, g_Csm); cudaGetSymbolAddress((void**)&pCsl, g_Csl);
    cudaGetSymbolAddress((void**)&pMCh, g_msgsCh); cudaGetSymbolAddress((void**)&pMCm, g_msgsCm); cudaGetSymbolAddress((void**)&pMCl, g_msgsCl);
    cudaGetSymbolAddress((void**)&pWCh, g_WCh); cudaGetSymbolAddress((void**)&pWCm, g_WCm); cudaGetSymbolAddress((void**)&pWCl, g_WCl);
    cudaGetSymbolAddress((void**)&pWLh, g_WLh); cudaGetSymbolAddress((void**)&pWLm, g_WLm); cudaGetSymbolAddress((void**)&pWLl, g_WLl);
    cudaGetSymbolAddress((void**)&pWlch, g_Wlch); cudaGetSymbolAddress((void**)&pWlcm, g_Wlcm); cudaGetSymbolAddress((void**)&pWlcl, g_Wlcl);
    cudaGetSymbolAddress((void**)&pWclh, g_Wclh); cudaGetSymbolAddress((void**)&pWclm, g_Wclm); cudaGetSymbolAddress((void**)&pWcll, g_Wcll);
    cudaGetSymbolAddress((void**)&pPre, g_pre);
    cudaGetSymbolAddress((void**)&pGates, g_gates);
    cudaGetSymbolAddress((void**)&pcC, g_cC);
    cudaGetSymbolAddress((void**)&pcL, g_cL);
    cudaGetSymbolAddress((void**)&pL32, g_L32);
    cudaGetSymbolAddress((void**)&pbC, g_bC);
    cudaGetSymbolAddress((void**)&pbL, g_bL);
    cudaGetSymbolAddress((void**)&pLitPtr, g_lit_ptr);
    cudaGetSymbolAddress((void**)&pClsPtr, g_cls_ptr);
    cudaGetSymbolAddress((void**)&pLitIdx, g_lit_idx);
    cudaGetSymbolAddress((void**)&pClsIdx, g_cls_idx);
    cudaGetSymbolAddress((void**)&pLitCnt, g_lit_cnt);
    cudaGetSymbolAddress((void**)&pClsCnt, g_cls_cnt);
    cudaGetSymbolAddress((void**)&pNnz, g_nnz);

    // init persistent split state + split weights
    init_s3<<<2048, 256>>>(L_state, hidden_L, hidden_C);
    prep_w_s3<<<512, 256>>>(W_lc, W_cl, WihC, WhhC, bihC, bhhC, WihL, WhhL, bihL, bhhL);

    // build CSR (both orientations) from dense M
    zero_i<<<64, 256>>>(pLitCnt, NLIT);
    zero_i<<<64, 256>>>(pClsCnt, NCLS);
    zero_i<<<1, 32>>>(pNnz, 1);
    build_pairs<<<dim3(4, NLIT), 256>>>(Mmat);
    scan_excl<<<1, 1024>>>(pLitCnt, pLitPtr, NLIT);
    scan_excl<<<1, 1024>>>(pClsCnt, pClsPtr, NCLS);
    zero_i<<<64, 256>>>(pLitCnt, NLIT);
    zero_i<<<64, 256>>>(pClsCnt, NCLS);
    fill_csr<<<512, 256>>>();

    for (int t = 0; t < 8; t++) {
        // LC_pre = L @ W_lc^T + b_lc                   (8064 x 128) fp32 out
        gemm_t3<<<dim3(2, NLITP / 128), 256>>>(
            pLh, pLm, pLl, nullptr, nullptr, nullptr, nullptr, nullptr, nullptr, 1,
            pWlch, pWlcm, pWlcl, b_lc, pPre, D);
        // clause msgs (fp32 accum, split out)          (16000 x 128)
        spmm_s3<<<NCLS, 128>>>(pClsPtr, pClsIdx, pPre, pMCh, pMCm, pMCl);
        // gates_C = [msgs|hC] @ WC^T + bC              (16000 x 512) fp32 out
        gemm_t3<<<dim3(8, NCLS / 128), 256>>>(
            pMCh, pMCm, pMCl, phCh, phCm, phCl, nullptr, nullptr, nullptr, 2,
            pWCh, pWCm, pWCl, pbC, pGates, GD);
        // Cs <- h_new (split) ; cC fp32 <- c_new ; hC <- split(c_new)
        lstm_s3<<<2048, 256>>>(pGates, pcC, pCsh, pCsm, pCsl, phCh, phCm, phCl,
                               nullptr, NCLS);
        // CL_pre = Cs @ W_cl^T + b_cl                  (16000 x 128) fp32 out
        gemm_t3<<<dim3(2, NCLS / 128), 256>>>(
            pCsh, pCsm, pCsl, nullptr, nullptr, nullptr, nullptr, nullptr, nullptr, 1,
            pWclh, pWclm, pWcll, b_cl, pPre, D);
        // literal msgs                                 (8000 x 128)
        spmm_s3<<<NLIT, 128>>>(pLitPtr, pLitIdx, pPre, pMLh, pMLm, pMLl);
        // gates_L = [msgs|L|hL] @ WL^T + bL            (8064 x 512) fp32 out
        gemm_t3<<<dim3(8, NLITP / 128), 256>>>(
            pMLh, pMLm, pMLl, pLh, pLm, pLl, phLh, phLm, phLl, 3,
            pWLh, pWLm, pWLl, pbL, pGates, GD);
        // L <- h_new (split + fp32) ; cL <- c_new ; hL <- split(c_new)
        lstm_s3<<<2048, 256>>>(pGates, pcL, pLh, pLm, pLl, phLh, phLm, phLl,
                               pL32, NLIT);
    }

    copy_f<<<1024, 256>>>(out, pL32, NLIT * D);
    (void)in_sizes; (void)n_in; (void)out_size;
}

// round 16
// speedup vs baseline: 1.6466x; 1.6466x over previous
#include <cuda_runtime.h>
#include <cuda_bf16.h>
#include <math.h>
#include <stdint.h>

#define D     128
#define NLIT  8000
#define NLITP 8064          // padded to 63*128
#define NCLS  16000         // = 125*128
#define GD    512
#define NNZ_MAX 480000

#define LDT 40              // smem tile row stride in bf16 (32 + 8 pad)
// per-stage smem layout (bytes): A = 3 * 128*LDT*2 = 30720, B = 3 * 64*LDT*2 = 15360
#define A_LVL_B   10240
#define B_LVL_B   5120
#define A_TOT_B   30720
#define STAGE_B   46080
#define SMEM_TOT  (2 * STAGE_B)
typedef __nv_bfloat16 bf16;

// ---------------- persistent scratch (device globals) -----------------------
__device__ bf16 g_Lh[NLITP*D],     g_Lm[NLITP*D],     g_Ll[NLITP*D];
__device__ bf16 g_hLh[NLITP*D],    g_hLm[NLITP*D],    g_hLl[NLITP*D];
__device__ bf16 g_msgsLh[NLITP*D], g_msgsLm[NLITP*D], g_msgsLl[NLITP*D];
__device__ bf16 g_hCh[NCLS*D],     g_hCm[NCLS*D],     g_hCl[NCLS*D];
__device__ bf16 g_Csh[NCLS*D],     g_Csm[NCLS*D],     g_Csl[NCLS*D];
__device__ bf16 g_msgsCh[NCLS*D],  g_msgsCm[NCLS*D],  g_msgsCl[NCLS*D];
__device__ bf16 g_WCh[GD*2*D],     g_WCm[GD*2*D],     g_WCl[GD*2*D];
__device__ bf16 g_WLh[GD*3*D],     g_WLm[GD*3*D],     g_WLl[GD*3*D];
__device__ bf16 g_Wlch[D*D],       g_Wlcm[D*D],       g_Wlcl[D*D];
__device__ bf16 g_Wclh[D*D],       g_Wclm[D*D],       g_Wcll[D*D];
__device__ float g_pre[NCLS * D];
__device__ float g_gates[NCLS * GD];
__device__ float g_cC[NCLS * D];
__device__ float g_cL[NLIT * D];
__device__ float g_L32[NLIT * D];
__device__ float g_bC[GD];
__device__ float g_bL[GD];
__device__ int g_lit_ptr[NLIT + 1];
__device__ int g_cls_ptr[NCLS + 1];
__device__ int g_lit_idx[NNZ_MAX];
__device__ int g_cls_idx[NNZ_MAX];
__device__ int g_lit_cnt[NLIT];
__device__ int g_cls_cnt[NCLS];
__device__ int g_pair_l[NNZ_MAX];
__device__ int g_pair_c[NNZ_MAX];
__device__ int g_nnz[1];

// ---------------- helpers ----------------------------------------------------
__device__ __forceinline__ uint32_t s2u(const void* p) {
    uint32_t a;
    asm("{ .reg .u64 t; cvta.to.shared.u64 t, %1; cvt.u32.u64 %0, t; }" : "=r"(a) : "l"(p));
    return a;
}

#define LDSM_X4(r0, r1, r2, r3, addr) \
    asm volatile("ldmatrix.sync.aligned.m8n8.x4.shared.b16 {%0,%1,%2,%3}, [%4];" \
                 : "=r"(r0), "=r"(r1), "=r"(r2), "=r"(r3) : "r"(addr))

#define MMAB(c, a, b0v, b1v) \
    asm volatile("mma.sync.aligned.m16n8k16.row.col.f32.bf16.bf16.f32 " \
                 "{%0,%1,%2,%3}, {%4,%5,%6,%7}, {%8,%9}, {%0,%1,%2,%3};" \
                 : "+f"((c)[0]), "+f"((c)[1]), "+f"((c)[2]), "+f"((c)[3]) \
                 : "r"((a)[0]), "r"((a)[1]), "r"((a)[2]), "r"((a)[3]), \
                   "r"(b0v), "r"(b1v))

#define CP16(dst_u32, src_ptr) \
    asm volatile("cp.async.cg.shared.global [%0], [%1], 16;" \
                 :: "r"(dst_u32), "l"(src_ptr) : "memory")
#define CP_COMMIT() asm volatile("cp.async.commit_group;" ::: "memory")
#define CP_WAIT0()  asm volatile("cp.async.wait_group 0;" ::: "memory")
#define CP_WAIT1()  asm volatile("cp.async.wait_group 1;" ::: "memory")

__device__ __forceinline__ void split3(float x, bf16& h, bf16& m, bf16& l) {
    h = __float2bfloat16_rn(x);
    float r1 = x - __bfloat162float(h);
    m = __float2bfloat16_rn(r1);
    float r2 = r1 - __bfloat162float(m);
    l = __float2bfloat16_rn(r2);
}

// -------- triple-split bf16 GEMM, per-step dd chains + cp.async pipeline ----
// C[M x N] = catA[M x K] * B[N x K]^T + bias, fp32 out.
// Per k-step, per output group: dd=0; chain 5 small correction MMAs (2^-8 and
// 2^-16 scale) then the hi*hi MMA; RN FADD dd into tot. Chained-op rounding
// acts on small accumulator values => unbiased ~u noise (validated class).
// CTA tile 128x64; 8 warps; warp tile 32x32; 2-stage cp.async double buffer.
__global__ void __launch_bounds__(256, 2) gemm_t3(
    const bf16* __restrict__ A0h, const bf16* __restrict__ A0m, const bf16* __restrict__ A0l,
    const bf16* __restrict__ A1h, const bf16* __restrict__ A1m, const bf16* __restrict__ A1l,
    const bf16* __restrict__ A2h, const bf16* __restrict__ A2m, const bf16* __restrict__ A2l,
    int nseg,
    const bf16* __restrict__ Bh, const bf16* __restrict__ Bm, const bf16* __restrict__ Bl,
    const float* __restrict__ bias, float* __restrict__ Cout, int N)
{
    extern __shared__ __align__(16) char smem[];
    const uint32_t sb = s2u(smem);
    const int tid = threadIdx.x;
    const int wid = tid >> 5, lid = tid & 31;
    const int warp_m = wid & 3, warp_n = wid >> 2;   // 4 x 2
    const int g  = lid >> 2, tg = lid & 3;
    const int quad = lid >> 3, lr = lid & 7;
    const int K = nseg * 128;
    const int m0 = blockIdx.y * 128, n0 = blockIdx.x * 64;
    const bf16* segA[3][3] = {{A0h, A1h, A2h}, {A0m, A1m, A2m}, {A0l, A1l, A2l}};
    const bf16* segB[3] = {Bh, Bm, Bl};

    float tot[2][4][4];
#pragma unroll
    for (int i = 0; i < 2; i++)
#pragma unroll
        for (int j = 0; j < 4; j++)
#pragma unroll
            for (int q = 0; q < 4; q++) tot[i][j][q] = 0.f;

    const int T = K >> 5;   // number of 32-wide k tiles

    // ---- async stage loader: 2304 16B transfers per stage, 9 per thread ----
    auto load_stage = [&](int st, int kt) {
        const int k0 = kt << 5;
        const int seg = k0 >> 7;
        const int ko = k0 & 127;
        const uint32_t base = sb + st * STAGE_B;
#pragma unroll
        for (int v = tid; v < 3 * 768; v += 256) {
            int lvl = v / 768;
            int rr = v % 768;
            int r = rr >> 2, c4 = rr & 3;
            if (r < 128) {
                uint32_t dst = base + lvl * A_LVL_B + (uint32_t)(r * LDT + c4 * 8) * 2;
                CP16(dst, segA[lvl][seg] + (size_t)(m0 + r) * 128 + ko + c4 * 8);
            } else {
                int rb = r - 128;
                uint32_t dst = base + A_TOT_B + lvl * B_LVL_B
                             + (uint32_t)(rb * LDT + c4 * 8) * 2;
                CP16(dst, segB[lvl] + (size_t)(n0 + rb) * K + k0 + c4 * 8);
            }
        }
    };

    load_stage(0, 0);
    CP_COMMIT();

    for (int it = 0; it < T; it++) {
        if (it + 1 < T) {
            load_stage((it + 1) & 1, it + 1);
            CP_COMMIT();
            CP_WAIT1();
        } else {
            CP_WAIT0();
        }
        __syncthreads();

        const uint32_t Asb = sb + (it & 1) * STAGE_B;
        const uint32_t Bsb = Asb + A_TOT_B;

#pragma unroll
        for (int kk = 0; kk < 32; kk += 16) {
            uint32_t a[3][2][4], b[3][2][4];
#pragma unroll
            for (int mt = 0; mt < 2; mt++) {
                uint32_t off = (uint32_t)((warp_m * 32 + mt * 16 + (quad & 1) * 8 + lr) * LDT
                                          + kk + (quad >> 1) * 8) * 2;
#pragma unroll
                for (int lvl = 0; lvl < 3; lvl++)
                    LDSM_X4(a[lvl][mt][0], a[lvl][mt][1], a[lvl][mt][2], a[lvl][mt][3],
                            Asb + lvl * A_LVL_B + off);
            }
#pragma unroll
            for (int p = 0; p < 2; p++) {
                uint32_t off = (uint32_t)((warp_n * 32 + p * 16 + (quad >> 1) * 8 + lr) * LDT
                                          + kk + (quad & 1) * 8) * 2;
#pragma unroll
                for (int lvl = 0; lvl < 3; lvl++)
                    LDSM_X4(b[lvl][p][0], b[lvl][p][1], b[lvl][p][2], b[lvl][p][3],
                            Bsb + lvl * B_LVL_B + off);
            }
#pragma unroll
            for (int mt = 0; mt < 2; mt++)
#pragma unroll
                for (int p = 0; p < 2; p++) {
                    float dd[4];
                    // group 2p: corrections first (small), hi*hi last, FADD out
                    dd[0] = dd[1] = dd[2] = dd[3] = 0.f;
#pragma unroll
                    for (int ia = 0; ia < 3; ia++)
#pragma unroll
                        for (int ib = 0; ib < 3; ib++) {
                            int s = ia + ib;
                            if (s < 1 || s > 2) continue;
                            MMAB(dd, a[ia][mt], b[ib][p][0], b[ib][p][1]);
                        }
                    MMAB(dd, a[0][mt], b[0][p][0], b[0][p][1]);
#pragma unroll
                    for (int q = 0; q < 4; q++) tot[mt][2*p][q] += dd[q];
                    // group 2p+1
                    dd[0] = dd[1] = dd[2] = dd[3] = 0.f;
#pragma unroll
                    for (int ia = 0; ia < 3; ia++)
#pragma unroll
                        for (int ib = 0; ib < 3; ib++) {
                            int s = ia + ib;
                            if (s < 1 || s > 2) continue;
                            MMAB(dd, a[ia][mt], b[ib][p][2], b[ib][p][3]);
                        }
                    MMAB(dd, a[0][mt], b[0][p][2], b[0][p][3]);
#pragma unroll
                    for (int q = 0; q < 4; q++) tot[mt][2*p+1][q] += dd[q];
                }
        }
        __syncthreads();
    }

    // epilogue: out = tot + bias (fp32)
#pragma unroll
    for (int mt = 0; mt < 2; mt++) {
        int row = m0 + warp_m * 32 + mt * 16 + g;
#pragma unroll
        for (int nt = 0; nt < 4; nt++) {
            int col = n0 + warp_n * 32 + nt * 8 + 2 * tg;
            float bx = bias[col], by = bias[col + 1];
            *(float2*)(Cout + (size_t)row * N + col) =
                make_float2(tot[mt][nt][0] + bx, tot[mt][nt][1] + by);
            *(float2*)(Cout + (size_t)(row + 8) * N + col) =
                make_float2(tot[mt][nt][2] + bx, tot[mt][nt][3] + by);
        }
    }
}

// ---------------- SpMM (gather, fp32 accum, triple-split output) ------------
__global__ void spmm_s3(const int* __restrict__ ptr, const int* __restrict__ idx,
                        const float* __restrict__ src,
                        bf16* __restrict__ dh, bf16* __restrict__ dm,
                        bf16* __restrict__ dl) {
    int row = blockIdx.x;
    int d = threadIdx.x;  // 128
    int s = ptr[row], e = ptr[row + 1];
    float acc = 0.f;
    for (int j = s; j < e; j++) acc += __ldg(&src[(size_t)idx[j] * D + d]);
    bf16 h, m, l;
    split3(acc, h, m, l);
    size_t o = (size_t)row * D + d;
    dh[o] = h; dm[o] = m; dl[o] = l;
}

// ---------------- LSTM pointwise (fp32 math, triple-split outputs) ----------
__device__ __forceinline__ float sigm(float x) { return 1.f / (1.f + expf(-x)); }

__global__ void lstm_s3(const float* __restrict__ gates, float* __restrict__ c,
                        bf16* __restrict__ hh, bf16* __restrict__ hm, bf16* __restrict__ hl,
                        bf16* __restrict__ ch, bf16* __restrict__ cm, bf16* __restrict__ cl,
                        float* __restrict__ h32, int rows) {
    int n = rows * D;
    int stride = gridDim.x * blockDim.x;
    for (int i = blockIdx.x * blockDim.x + threadIdx.x; i < n; i += stride) {
        int row = i >> 7, d = i & 127;
        const float* gr = gates + (size_t)row * GD;
        float ig = gr[d], fg = gr[D + d], gg = gr[2 * D + d], og = gr[3 * D + d];
        float cn = sigm(fg) * c[i] + sigm(ig) * tanhf(gg);
        c[i] = cn;
        bf16 xh, xm, xl;
        split3(cn, xh, xm, xl);
        ch[i] = xh; cm[i] = xm; cl[i] = xl;
        float hn = sigm(og) * tanhf(cn);
        split3(hn, xh, xm, xl);
        hh[i] = xh; hm[i] = xm; hl[i] = xl;
        if (h32) h32[i] = hn;
    }
}

// ---------------- init / weight prep ----------------------------------------
__global__ void init_s3(const float* __restrict__ L, const float* __restrict__ hL,
                        const float* __restrict__ hC) {
    int stride = gridDim.x * blockDim.x;
    for (int i = blockIdx.x * blockDim.x + threadIdx.x; i < NCLS * D; i += stride) {
        bf16 xh, xm, xl;
        if (i < NLITP * D) {
            int r = i >> 7;
            float lv = (r < NLIT) ? L[i] : 0.f;
            float hv = (r < NLIT) ? hL[i] : 0.f;
            split3(lv, xh, xm, xl); g_Lh[i] = xh;  g_Lm[i] = xm;  g_Ll[i] = xl;
            split3(hv, xh, xm, xl); g_hLh[i] = xh; g_hLm[i] = xm; g_hLl[i] = xl;
            bf16 z = __float2bfloat16_rn(0.f);
            g_msgsLh[i] = z; g_msgsLm[i] = z; g_msgsLl[i] = z;
            if (r < NLIT) g_cL[i] = hv;
        }
        float cv = hC[i];
        split3(cv, xh, xm, xl);
        g_hCh[i] = xh; g_hCm[i] = xm; g_hCl[i] = xl;
        g_cC[i] = cv;
    }
}

__global__ void prep_w_s3(const float* __restrict__ Wlc, const float* __restrict__ Wcl,
                          const float* __restrict__ WihC, const float* __restrict__ WhhC,
                          const float* __restrict__ bihC, const float* __restrict__ bhhC,
                          const float* __restrict__ WihL, const float* __restrict__ WhhL,
                          const float* __restrict__ bihL, const float* __restrict__ bhhL) {
    int stride = gridDim.x * blockDim.x;
    int tid0 = blockIdx.x * blockDim.x + threadIdx.x;
    bf16 xh, xm, xl;
    for (int t = tid0; t < GD * 2 * D; t += stride) {
        int j = t / (2 * D), k = t % (2 * D);
        float v = (k < D) ? WihC[j * D + k] : WhhC[j * D + (k - D)];
        split3(v, xh, xm, xl); g_WCh[t] = xh; g_WCm[t] = xm; g_WCl[t] = xl;
    }
    for (int t = tid0; t < GD * 3 * D; t += stride) {
        int j = t / (3 * D), k = t % (3 * D);
        float v = (k < 2 * D) ? WihL[j * 2 * D + k] : WhhL[j * D + (k - 2 * D)];
        split3(v, xh, xm, xl); g_WLh[t] = xh; g_WLm[t] = xm; g_WLl[t] = xl;
    }
    for (int t = tid0; t < D * D; t += stride) {
        split3(Wlc[t], xh, xm, xl); g_Wlch[t] = xh; g_Wlcm[t] = xm; g_Wlcl[t] = xl;
        split3(Wcl[t], xh, xm, xl); g_Wclh[t] = xh; g_Wclm[t] = xm; g_Wcll[t] = xl;
    }
    for (int t = tid0; t < GD; t += stride) {
        g_bC[t] = bihC[t] + bhhC[t];
        g_bL[t] = bihL[t] + bhhL[t];
    }
}

// ---------------- misc utility ----------------------------------------------
__global__ void copy_f(float* __restrict__ dst, const float* __restrict__ src, int n) {
    int stride = gridDim.x * blockDim.x;
    for (int i = blockIdx.x * blockDim.x + threadIdx.x; i < n; i += stride)
        dst[i] = src[i];
}
__global__ void zero_i(int* __restrict__ p, int n) {
    int stride = gridDim.x * blockDim.x;
    for (int i = blockIdx.x * blockDim.x + threadIdx.x; i < n; i += stride)
        p[i] = 0;
}

// ---------------- CSR build (validated) --------------------------------------
__global__ void build_pairs(const float* __restrict__ M) {
    int l = blockIdx.y;
    const float4* row = (const float4*)(M + (size_t)l * NCLS);
    const int total4 = NCLS / 4;
    int lane = threadIdx.x & 31;
    int stride = gridDim.x * blockDim.x;
    int row_count = 0;
    for (int i = blockIdx.x * blockDim.x + threadIdx.x;; i += stride) {
        bool inb = i < total4;
        if (__ballot_sync(0xffffffffu, inb) == 0) break;
        float4 v = inb ? row[i] : make_float4(0.f, 0.f, 0.f, 0.f);
        float vv[4] = {v.x, v.y, v.z, v.w};
#pragma unroll
        for (int j = 0; j < 4; j++) {
            bool pred = vv[j] > 0.5f;
            unsigned act = __ballot_sync(0xffffffffu, pred);
            int tot = __popc(act);
            if (pred) {
                int rank = __popc(act & ((1u << lane) - 1u));
                int leader = __ffs(act) - 1;
                int base = 0;
                if (lane == leader) base = atomicAdd(&g_nnz[0], tot);
                base = __shfl_sync(act, base, leader);
                int p = base + rank;
                int c = i * 4 + j;
                if (p < NNZ_MAX) { g_pair_l[p] = l; g_pair_c[p] = c; }
                atomicAdd(&g_cls_cnt[c], 1);
            }
            row_count += tot;
        }
    }
    if (lane == 0 && row_count) atomicAdd(&g_lit_cnt[l], row_count);
}

__global__ void scan_excl(const int* __restrict__ cnt, int* __restrict__ ptr, int n) {
    const int T = 1024;
    __shared__ int part[T];
    int t = threadIdx.x;
    int chunk = (n + T - 1) / T;
    int s0 = t * chunk;
    int s1 = min(n, s0 + chunk);
    int s = 0;
    for (int i = s0; i < s1; i++) s += cnt[i];
    part[t] = s;
    __syncthreads();
    if (t == 0) {
        int run = 0;
        for (int i = 0; i < T; i++) { int v = part[i]; part[i] = run; run += v; }
        ptr[n] = run;
    }
    __syncthreads();
    int run = part[t];
    for (int i = s0; i < s1; i++) { ptr[i] = run; run += cnt[i]; }
}

__global__ void fill_csr() {
    int nnz = g_nnz[0];
    if (nnz > NNZ_MAX) nnz = NNZ_MAX;
    int stride = gridDim.x * blockDim.x;
    for (int i = blockIdx.x * blockDim.x + threadIdx.x; i < nnz; i += stride) {
        int l = g_pair_l[i], c = g_pair_c[i];
        int p = g_lit_ptr[l] + atomicAdd(&g_lit_cnt[l], 1);
        g_lit_idx[p] = c;
        int q = g_cls_ptr[c] + atomicAdd(&g_cls_cnt[c], 1);
        g_cls_idx[q] = l;
    }
}

// ---------------- driver ----------------------------------------------------
extern "C" void kernel_launch(void* const* d_in, const int* in_sizes, int n_in,
                              void* d_out, int out_size) {
    const float* L_state  = (const float*)d_in[0];
    const float* hidden_L = (const float*)d_in[2];
    const float* hidden_C = (const float*)d_in[3];
    const float* Mmat     = (const float*)d_in[4];
    const float* W_lc = (const float*)d_in[6];
    const float* b_lc = (const float*)d_in[7];
    const float* W_cl = (const float*)d_in[8];
    const float* b_cl = (const float*)d_in[9];
    const float* WihC = (const float*)d_in[10];
    const float* WhhC = (const float*)d_in[11];
    const float* bihC = (const float*)d_in[12];
    const float* bhhC = (const float*)d_in[13];
    const float* WihL = (const float*)d_in[14];
    const float* WhhL = (const float*)d_in[15];
    const float* bihL = (const float*)d_in[16];
    const float* bhhL = (const float*)d_in[17];
    float* out = (float*)d_out;

    bf16 *pLh,*pLm,*pLl,*phLh,*phLm,*phLl,*pMLh,*pMLm,*pMLl;
    bf16 *phCh,*phCm,*phCl,*pCsh,*pCsm,*pCsl,*pMCh,*pMCm,*pMCl;
    bf16 *pWCh,*pWCm,*pWCl,*pWLh,*pWLm,*pWLl,*pWlch,*pWlcm,*pWlcl,*pWclh,*pWclm,*pWcll;
    float *pPre,*pGates,*pcC,*pcL,*pL32,*pbC,*pbL;
    int *pLitPtr,*pClsPtr,*pLitIdx,*pClsIdx,*pLitCnt,*pClsCnt,*pNnz;
    cudaGetSymbolAddress((void**)&pLh, g_Lh);   cudaGetSymbolAddress((void**)&pLm, g_Lm);   cudaGetSymbolAddress((void**)&pLl, g_Ll);
    cudaGetSymbolAddress((void**)&phLh, g_hLh); cudaGetSymbolAddress((void**)&phLm, g_hLm); cudaGetSymbolAddress((void**)&phLl, g_hLl);
    cudaGetSymbolAddress((void**)&pMLh, g_msgsLh); cudaGetSymbolAddress((void**)&pMLm, g_msgsLm); cudaGetSymbolAddress((void**)&pMLl, g_msgsLl);
    cudaGetSymbolAddress((void**)&phCh, g_hCh); cudaGetSymbolAddress((void**)&phCm, g_hCm); cudaGetSymbolAddress((void**)&phCl, g_hCl);
    cudaGetSymbolAddress((void**)&pCsh, g_Csh); cudaGetSymbolAddress((void**)&pCsm, g_Csm); cudaGetSymbolAddress((void**)&pCsl, g_Csl);
    cudaGetSymbolAddress((void**)&pMCh, g_msgsCh); cudaGetSymbolAddress((void**)&pMCm, g_msgsCm); cudaGetSymbolAddress((void**)&pMCl, g_msgsCl);
    cudaGetSymbolAddress((void**)&pWCh, g_WCh); cudaGetSymbolAddress((void**)&pWCm, g_WCm); cudaGetSymbolAddress((void**)&pWCl, g_WCl);
    cudaGetSymbolAddress((void**)&pWLh, g_WLh); cudaGetSymbolAddress((void**)&pWLm, g_WLm); cudaGetSymbolAddress((void**)&pWLl, g_WLl);
    cudaGetSymbolAddress((void**)&pWlch, g_Wlch); cudaGetSymbolAddress((void**)&pWlcm, g_Wlcm); cudaGetSymbolAddress((void**)&pWlcl, g_Wlcl);
    cudaGetSymbolAddress((void**)&pWclh, g_Wclh); cudaGetSymbolAddress((void**)&pWclm, g_Wclm); cudaGetSymbolAddress((void**)&pWcll, g_Wcll);
    cudaGetSymbolAddress((void**)&pPre, g_pre);
    cudaGetSymbolAddress((void**)&pGates, g_gates);
    cudaGetSymbolAddress((void**)&pcC, g_cC);
    cudaGetSymbolAddress((void**)&pcL, g_cL);
    cudaGetSymbolAddress((void**)&pL32, g_L32);
    cudaGetSymbolAddress((void**)&pbC, g_bC);
    cudaGetSymbolAddress((void**)&pbL, g_bL);
    cudaGetSymbolAddress((void**)&pLitPtr, g_lit_ptr);
    cudaGetSymbolAddress((void**)&pClsPtr, g_cls_ptr);
    cudaGetSymbolAddress((void**)&pLitIdx, g_lit_idx);
    cudaGetSymbolAddress((void**)&pClsIdx, g_cls_idx);
    cudaGetSymbolAddress((void**)&pLitCnt, g_lit_cnt);
    cudaGetSymbolAddress((void**)&pClsCnt, g_cls_cnt);
    cudaGetSymbolAddress((void**)&pNnz, g_nnz);

    cudaFuncSetAttribute(gemm_t3, cudaFuncAttributeMaxDynamicSharedMemorySize, SMEM_TOT);

    // init persistent split state + split weights
    init_s3<<<2048, 256>>>(L_state, hidden_L, hidden_C);
    prep_w_s3<<<512, 256>>>(W_lc, W_cl, WihC, WhhC, bihC, bhhC, WihL, WhhL, bihL, bhhL);

    // build CSR (both orientations) from dense M
    zero_i<<<64, 256>>>(pLitCnt, NLIT);
    zero_i<<<64, 256>>>(pClsCnt, NCLS);
    zero_i<<<1, 32>>>(pNnz, 1);
    build_pairs<<<dim3(4, NLIT), 256>>>(Mmat);
    scan_excl<<<1, 1024>>>(pLitCnt, pLitPtr, NLIT);
    scan_excl<<<1, 1024>>>(pClsCnt, pClsPtr, NCLS);
    zero_i<<<64, 256>>>(pLitCnt, NLIT);
    zero_i<<<64, 256>>>(pClsCnt, NCLS);
    fill_csr<<<512, 256>>>();

    for (int t = 0; t < 8; t++) {
        // LC_pre = L @ W_lc^T + b_lc                   (8064 x 128) fp32 out
        gemm_t3<<<dim3(2, NLITP / 128), 256, SMEM_TOT>>>(
            pLh, pLm, pLl, nullptr, nullptr, nullptr, nullptr, nullptr, nullptr, 1,
            pWlch, pWlcm, pWlcl, b_lc, pPre, D);
        // clause msgs (fp32 accum, split out)          (16000 x 128)
        spmm_s3<<<NCLS, 128>>>(pClsPtr, pClsIdx, pPre, pMCh, pMCm, pMCl);
        // gates_C = [msgs|hC] @ WC^T + bC              (16000 x 512) fp32 out
        gemm_t3<<<dim3(8, NCLS / 128), 256, SMEM_TOT>>>(
            pMCh, pMCm, pMCl, phCh, phCm, phCl, nullptr, nullptr, nullptr, 2,
            pWCh, pWCm, pWCl, pbC, pGates, GD);
        // Cs <- h_new (split) ; cC fp32 <- c_new ; hC <- split(c_new)
        lstm_s3<<<2048, 256>>>(pGates, pcC, pCsh, pCsm, pCsl, phCh, phCm, phCl,
                               nullptr, NCLS);
        // CL_pre = Cs @ W_cl^T + b_cl                  (16000 x 128) fp32 out
        gemm_t3<<<dim3(2, NCLS / 128), 256, SMEM_TOT>>>(
            pCsh, pCsm, pCsl, nullptr, nullptr, nullptr, nullptr, nullptr, nullptr, 1,
            pWclh, pWclm, pWcll, b_cl, pPre, D);
        // literal msgs                                 (8000 x 128)
        spmm_s3<<<NLIT, 128>>>(pLitPtr, pLitIdx, pPre, pMLh, pMLm, pMLl);
        // gates_L = [msgs|L|hL] @ WL^T + bL            (8064 x 512) fp32 out
        gemm_t3<<<dim3(8, NLITP / 128), 256, SMEM_TOT>>>(
            pMLh, pMLm, pMLl, pLh, pLm, pLl, phLh, phLm, phLl, 3,
            pWLh, pWLm, pWLl, pbL, pGates, GD);
        // L <- h_new (split + fp32) ; cL <- c_new ; hL <- split(c_new)
        lstm_s3<<<2048, 256>>>(pGates, pcL, pLh, pLm, pLl, phLh, phLm, phLl,
                               pL32, NLIT);
    }

    copy_f<<<1024, 256>>>(out, pL32, NLIT * D);
    (void)in_sizes; (void)n_in; (void)out_size;
}